// round 13
// baseline (speedup 1.0000x reference)
#include <cuda_runtime.h>
#include <cuda_bf16.h>
#include <math.h>
#include <stdint.h>

#define GMM_D 64
#define GMM_K 64
#define BS    128
#define TPB   128
#define NJ2   16          // ulonglong2 steps (64 floats = 32 pairs = 16 ull2)
#define RX    129         // X tile row stride (ull2)
#define RW    65          // W tile row stride (ull2)
#define SCR_STRIDE 36     // transpose scratch row stride (floats): 144B, 16B-aligned
#define SCR_WARP   2304   // bytes per warp per pass (16 rows x 36 floats x 4B)

typedef unsigned long long ull;

// smem offsets (bytes)
#define OFF_X0   0
#define OFF_X1   33024
#define OFF_WB   66048
#define OFF_WA   82688    // 16640 B; doubles as transpose scratch in fast path
#define OFF_C    99328
#define OFF_FLAG 99584
#define SMEM_TOTAL 99600  // x2 CTAs = 199.2KB <= 228KB/SM

__device__ __forceinline__ ull fma2(ull a, ull b, ull c) {
    ull d; asm("fma.rn.f32x2 %0, %1, %2, %3;" : "=l"(d) : "l"(a), "l"(b), "l"(c)); return d;
}
__device__ __forceinline__ ull mul2(ull a, ull b) {
    ull d; asm("mul.rn.f32x2 %0, %1, %2;" : "=l"(d) : "l"(a), "l"(b)); return d;
}
__device__ __forceinline__ ull pack2(float lo, float hi) {
    ull r; asm("mov.b64 %0, {%1, %2};" : "=l"(r) : "f"(lo), "f"(hi)); return r;
}
__device__ __forceinline__ void unpack2(ull v, float& lo, float& hi) {
    asm("mov.b64 {%0, %1}, %2;" : "=f"(lo), "=f"(hi) : "l"(v));
}
__device__ __forceinline__ uint32_t smem_u32(const void* p) {
    uint32_t a;
    asm("{ .reg .u64 t; cvta.to.shared.u64 t, %1; cvt.u32.u64 %0, t; }" : "=r"(a) : "l"(p));
    return a;
}
__device__ __forceinline__ void cp_async16(uint32_t dst, const void* src) {
    asm volatile("cp.async.cg.shared.global [%0], [%1], 16;" :: "r"(dst), "l"(src));
}
__device__ __forceinline__ void cp_commit() {
    asm volatile("cp.async.commit_group;" ::: "memory");
}
template <int NN>
__device__ __forceinline__ void cp_wait() {
    asm volatile("cp.async.wait_group %0;" :: "n"(NN) : "memory");
}

// stage one 128-sample X tile (jp2-major ull2 layout) via cp.async
__device__ __forceinline__ void prefetch_tile(const float* __restrict__ X, int tile,
                                              char* smbase, int xoff, int t) {
    const char* src = (const char*)(X + (size_t)tile * BS * GMM_D);
    #pragma unroll
    for (int i = 0; i < 16; i++) {
        int c   = i * TPB + t;            // 0..2047 16B chunks
        int n   = c >> 4;
        int jp2 = c & 15;
        uint32_t dst = smem_u32(smbase + xoff + (jp2 * RX + n) * 16);
        cp_async16(dst, src + (size_t)c * 16);
    }
}

// ---------------------------------------------------------------------------
// Persistent fused GMM posterior, warp-local epilogue.
// weighted[n,k] = sum_d x*B[k] (+ x^2*A'[k] if logvars not k-uniform) + C[k];
// k-uniform terms cancel in the log-softmax over k.
// Lane map: sg=lane&3 (sample), kg=lane>>2 (k-group).
//   samples: n = n0 + 32*warp + sg + 4m  (m=0..7)  -> warp owns 32 samples
//   k:       k = kg + 8q                (q=0..7)  -> warp owns all 64 k
// logsumexp over k = per-thread over q + shfl-xor over kg (lanes 4,8,16).
// ---------------------------------------------------------------------------
__global__ void __launch_bounds__(TPB, 2)
gmm_persist(const float* __restrict__ X, const float* __restrict__ mu,
            const float* __restrict__ lv, const float* __restrict__ lp,
            float* __restrict__ out, int N, int ntiles) {
    extern __shared__ char sm[];
    ulonglong2* sWB = (ulonglong2*)(sm + OFF_WB);
    ulonglong2* sWA = (ulonglong2*)(sm + OFF_WA);
    float* sC   = (float*)(sm + OFF_C);
    int*   sFlag= (int*)(sm + OFF_FLAG);

    const int t    = threadIdx.x;
    const int warp = t >> 5;
    const int lane = t & 31;
    const int sg   = lane & 3;
    const int kg   = lane >> 2;

    if (t == 0) *sFlag = 0;
    __syncthreads();

    // ---- stage W tiles + uniformity flag + C[k] (once per CTA) ----
    {
        const float4* mu4 = (const float4*)mu;
        const float4* lv4 = (const float4*)lv;
        int bad = 0;
        #pragma unroll
        for (int i = 0; i < 8; i++) {
            int idx = i * TPB + t;        // 0..1023
            int jp2 = idx & 15;
            int k   = idx >> 4;
            float4 l  = lv4[k * 16 + jp2];
            float4 m  = mu4[k * 16 + jp2];
            float4 l0 = lv4[jp2];
            bad |= (__float_as_int(l.x) != __float_as_int(l0.x)) |
                   (__float_as_int(l.y) != __float_as_int(l0.y)) |
                   (__float_as_int(l.z) != __float_as_int(l0.z)) |
                   (__float_as_int(l.w) != __float_as_int(l0.w));
            float e0 = __expf(-l.x), e1 = __expf(-l.y);
            float e2 = __expf(-l.z), e3 = __expf(-l.w);
            ulonglong2 B, A;
            B.x = pack2(m.x * e0, m.y * e1);     B.y = pack2(m.z * e2, m.w * e3);
            A.x = pack2(-0.5f * e0, -0.5f * e1); A.y = pack2(-0.5f * e2, -0.5f * e3);
            sWB[jp2 * RW + k] = B;
            sWA[jp2 * RW + k] = A;
        }
        if (bad) atomicOr(sFlag, 1);
        if (t < GMM_K) {
            float s = 0.f;
            #pragma unroll 8
            for (int d = 0; d < GMM_D; d++) {
                float l = lv[t * GMM_D + d];
                float m = mu[t * GMM_D + d];
                s += l + m * m * __expf(-l);
            }
            sC[t] = -0.5f * s + lp[t];
        }
    }
    __syncthreads();

    const int general = *sFlag;
    float ck[8];
    #pragma unroll
    for (int q = 0; q < 8; q++) ck[q] = sC[kg + 8 * q];

    // ---- prefetch first tile ----
    const int stride = gridDim.x;
    int tile = blockIdx.x;
    if (tile < ntiles) prefetch_tile(X, tile, sm, OFF_X0, t);
    cp_commit();

    int bufi = 0;
    for (; tile < ntiles; tile += stride) {
        __syncthreads();                  // all warps done reading buf[bufi^1] (prev GEMM)
        const int nxt = tile + stride;
        const int curoff = bufi ? OFF_X1 : OFF_X0;
        if (nxt < ntiles) {
            prefetch_tile(X, nxt, sm, bufi ? OFF_X0 : OFF_X1, t);
            cp_commit();
            cp_wait<1>();
        } else {
            cp_wait<0>();
        }
        __syncthreads();                  // current X buf visible to all threads

        const ulonglong2* xb = (const ulonglong2*)(sm + curoff) + 32 * warp + sg;
        const ulonglong2* wb = sWB + kg;
        const ulonglong2* wa = sWA + kg;

        ull acc[8][8];
        #pragma unroll
        for (int m = 0; m < 8; m++)
            #pragma unroll
            for (int q = 0; q < 8; q++) acc[m][q] = 0ull;

        if (!general) {
            #pragma unroll
            for (int jp2 = 0; jp2 < NJ2; jp2++) {
                ulonglong2 wv[8], xv[8];
                #pragma unroll
                for (int q = 0; q < 8; q++) wv[q] = wb[jp2 * RW + 8 * q];
                #pragma unroll
                for (int m = 0; m < 8; m++) xv[m] = xb[jp2 * RX + 4 * m];
                #pragma unroll
                for (int m = 0; m < 8; m++)
                    #pragma unroll
                    for (int q = 0; q < 8; q++) {
                        acc[m][q] = fma2(xv[m].x, wv[q].x, acc[m][q]);
                        acc[m][q] = fma2(xv[m].y, wv[q].y, acc[m][q]);
                    }
            }
        } else {
            #pragma unroll 2
            for (int jp2 = 0; jp2 < NJ2; jp2++) {
                ulonglong2 wv[8], wv2[8], xv[8];
                #pragma unroll
                for (int q = 0; q < 8; q++) { wv[q]  = wb[jp2 * RW + 8 * q];
                                              wv2[q] = wa[jp2 * RW + 8 * q]; }
                #pragma unroll
                for (int m = 0; m < 8; m++) xv[m] = xb[jp2 * RX + 4 * m];
                #pragma unroll
                for (int m = 0; m < 8; m++) {
                    ull xqx = mul2(xv[m].x, xv[m].x);
                    ull xqy = mul2(xv[m].y, xv[m].y);
                    #pragma unroll
                    for (int q = 0; q < 8; q++) {
                        acc[m][q] = fma2(xv[m].x, wv[q].x, acc[m][q]);
                        acc[m][q] = fma2(xv[m].y, wv[q].y, acc[m][q]);
                        acc[m][q] = fma2(xqx, wv2[q].x, acc[m][q]);
                        acc[m][q] = fma2(xqy, wv2[q].y, acc[m][q]);
                    }
                }
            }
        }

        // ---- finalize weighted values ----
        float w[8][8];
        #pragma unroll
        for (int q = 0; q < 8; q++)
            #pragma unroll
            for (int m = 0; m < 8; m++) {
                float lo, hi; unpack2(acc[m][q], lo, hi);
                w[m][q] = lo + hi + ck[q];
            }

        // ---- warp-local logsumexp over k (shfl over kg = lane bits 2..4) ----
        float lse[8];
        #pragma unroll
        for (int m = 0; m < 8; m++) {
            float mx = w[m][0];
            #pragma unroll
            for (int q = 1; q < 8; q++) mx = fmaxf(mx, w[m][q]);
            mx = fmaxf(mx, __shfl_xor_sync(0xffffffffu, mx, 4));
            mx = fmaxf(mx, __shfl_xor_sync(0xffffffffu, mx, 8));
            mx = fmaxf(mx, __shfl_xor_sync(0xffffffffu, mx, 16));
            float s = 0.f;
            #pragma unroll
            for (int q = 0; q < 8; q++) s += __expf(w[m][q] - mx);
            s += __shfl_xor_sync(0xffffffffu, s, 4);
            s += __shfl_xor_sync(0xffffffffu, s, 8);
            s += __shfl_xor_sync(0xffffffffu, s, 16);
            lse[m] = mx + __logf(s);
        }

        // ---- per-warp transpose scratch -> coalesced STG.128 ----
        if (general) __syncthreads();     // scratch lives in current X buf: wait all GEMM reads
        float* scr = (float*)(sm + (general ? curoff : OFF_WA) + warp * SCR_WARP);
        const int n0 = tile * BS;
        #pragma unroll
        for (int p = 0; p < 4; p++) {     // 4 passes of 16 k-rows (q = 2p, 2p+1)
            #pragma unroll
            for (int qq = 0; qq < 2; qq++) {
                const int q = 2 * p + qq;
                const int r = kg + 8 * qq;                 // row 0..15 within pass
                #pragma unroll
                for (int m = 0; m < 8; m++)
                    scr[r * SCR_STRIDE + sg + 4 * m] = w[m][q] - lse[m];
            }
            __syncwarp();
            #pragma unroll
            for (int j = 0; j < 4; j++) {
                const int r = j * 4 + (lane >> 3);
                const int c = 4 * (lane & 7);
                float4 v = *(const float4*)&scr[r * SCR_STRIDE + c];
                *(float4*)(out + (size_t)(16 * p + r) * N + n0 + 32 * warp + c) = v;
            }
            __syncwarp();
        }
        bufi ^= 1;
    }
}

extern "C" void kernel_launch(void* const* d_in, const int* in_sizes, int n_in,
                              void* d_out, int out_size) {
    const float* X  = (const float*)d_in[0];
    const float* mu = (const float*)d_in[1];
    const float* lv = (const float*)d_in[2];
    const float* lp = (const float*)d_in[3];
    float* out = (float*)d_out;

    const int K = in_sizes[3];            // 64
    const int D = in_sizes[1] / K;        // 64
    const int N = in_sizes[0] / D;        // 131072

    const int ntiles = N / BS;            // 1024
    int grid = 296;                       // 2 per SM x 148 SMs
    if (grid > ntiles) grid = ntiles;

    cudaFuncSetAttribute(gmm_persist, cudaFuncAttributeMaxDynamicSharedMemorySize, SMEM_TOTAL);
    gmm_persist<<<grid, TPB, SMEM_TOTAL>>>(X, mu, lv, lp, out, N, ntiles);
}

// round 14
// speedup vs baseline: 1.0047x; 1.0047x over previous
#include <cuda_runtime.h>
#include <cuda_bf16.h>
#include <math.h>
#include <stdint.h>

#define GMM_D 64
#define GMM_K 64
#define TPB   128
#define WCH   32          // samples per warp-chunk
#define NJ2   16          // ulonglong2 steps (64 floats = 32 pairs = 16 ull2)
#define RXC   33          // chunk row stride (ull2): 528B
#define RW    65          // W tile row stride (ull2): 1040B
#define SCR_STRIDE 36     // transpose scratch row stride (floats)

typedef unsigned long long ull;

// smem offsets (bytes)
#define XBUF_BYTES 8448                   // 16 * 33 * 16
#define OFF_XB   0                        // 4 warps x 2 bufs x 8448 = 67584
#define OFF_WB   67584                    // 16640
#define OFF_WA   84224                    // 16640
#define OFF_C    100864                   // 256
#define OFF_SCR  101120                   // 4 x 2304 = 9216
#define OFF_FLAG 110336
#define SMEM_TOTAL 110352                 // x2 CTAs = 220.7KB <= 228KB

__device__ __forceinline__ ull fma2(ull a, ull b, ull c) {
    ull d; asm("fma.rn.f32x2 %0, %1, %2, %3;" : "=l"(d) : "l"(a), "l"(b), "l"(c)); return d;
}
__device__ __forceinline__ ull mul2(ull a, ull b) {
    ull d; asm("mul.rn.f32x2 %0, %1, %2;" : "=l"(d) : "l"(a), "l"(b)); return d;
}
__device__ __forceinline__ ull pack2(float lo, float hi) {
    ull r; asm("mov.b64 %0, {%1, %2};" : "=l"(r) : "f"(lo), "f"(hi)); return r;
}
__device__ __forceinline__ void unpack2(ull v, float& lo, float& hi) {
    asm("mov.b64 {%0, %1}, %2;" : "=f"(lo), "=f"(hi) : "l"(v));
}
__device__ __forceinline__ uint32_t smem_u32(const void* p) {
    uint32_t a;
    asm("{ .reg .u64 t; cvta.to.shared.u64 t, %1; cvt.u32.u64 %0, t; }" : "=r"(a) : "l"(p));
    return a;
}
__device__ __forceinline__ void cp_async16(uint32_t dst, const void* src) {
    asm volatile("cp.async.cg.shared.global [%0], [%1], 16;" :: "r"(dst), "l"(src));
}
__device__ __forceinline__ void cp_commit() {
    asm volatile("cp.async.commit_group;" ::: "memory");
}
template <int NN>
__device__ __forceinline__ void cp_wait() {
    asm volatile("cp.async.wait_group %0;" :: "n"(NN) : "memory");
}

// stage one 32-sample chunk (jp2-major ull2 layout) into a per-warp buffer
__device__ __forceinline__ void prefetch_chunk(const float* __restrict__ X, int chunk,
                                               uint32_t dstbase, int lane) {
    const char* src = (const char*)(X + (size_t)chunk * WCH * GMM_D);
    #pragma unroll
    for (int i = 0; i < 16; i++) {
        int c   = i * 32 + lane;          // 0..511 16B chunks
        int n   = c >> 4;
        int jp2 = c & 15;
        cp_async16(dstbase + (uint32_t)(jp2 * RXC + n) * 16, src + (size_t)c * 16);
    }
}

// ---------------------------------------------------------------------------
// Warp-autonomous persistent GMM posterior.
// weighted[n,k] = sum_d x*B[k] (+ x^2*A'[k] if logvars not k-uniform) + C[k];
// k-uniform terms cancel in the log-softmax over k.
// Each WARP independently streams 32-sample chunks (own double-buffered
// cp.async staging, no __syncthreads after init).
// Lane map: sg=lane&3 (sample), kg=lane>>2 (k-group).
//   samples: n = chunk*32 + sg + 4m  (m=0..7); k = kg + 8q (q=0..7).
// ---------------------------------------------------------------------------
__global__ void __launch_bounds__(TPB, 2)
gmm_warp(const float* __restrict__ X, const float* __restrict__ mu,
         const float* __restrict__ lv, const float* __restrict__ lp,
         float* __restrict__ out, int N, int nchunks, int nwarps) {
    extern __shared__ char sm[];
    ulonglong2* sWB = (ulonglong2*)(sm + OFF_WB);
    ulonglong2* sWA = (ulonglong2*)(sm + OFF_WA);
    float* sC   = (float*)(sm + OFF_C);
    int*   sFlag= (int*)(sm + OFF_FLAG);

    const int t    = threadIdx.x;
    const int warp = t >> 5;
    const int lane = t & 31;
    const int sg   = lane & 3;
    const int kg   = lane >> 2;

    const uint32_t buf0 = smem_u32(sm) + OFF_XB + warp * 2 * XBUF_BYTES;
    const uint32_t buf1 = buf0 + XBUF_BYTES;

    // kick off first chunk prefetch immediately
    const int gwarp = blockIdx.x * 4 + warp;
    if (gwarp < nchunks) prefetch_chunk(X, gwarp, buf0, lane);
    cp_commit();

    if (t == 0) *sFlag = 0;
    __syncthreads();

    // ---- stage W tiles + uniformity flag + C[k] (once per CTA) ----
    {
        const float4* mu4 = (const float4*)mu;
        const float4* lv4 = (const float4*)lv;
        int bad = 0;
        #pragma unroll
        for (int i = 0; i < 8; i++) {
            int idx = i * TPB + t;        // 0..1023
            int jp2 = idx & 15;
            int k   = idx >> 4;
            float4 l  = lv4[k * 16 + jp2];
            float4 m  = mu4[k * 16 + jp2];
            float4 l0 = lv4[jp2];
            bad |= (__float_as_int(l.x) != __float_as_int(l0.x)) |
                   (__float_as_int(l.y) != __float_as_int(l0.y)) |
                   (__float_as_int(l.z) != __float_as_int(l0.z)) |
                   (__float_as_int(l.w) != __float_as_int(l0.w));
            float e0 = __expf(-l.x), e1 = __expf(-l.y);
            float e2 = __expf(-l.z), e3 = __expf(-l.w);
            ulonglong2 B, A;
            B.x = pack2(m.x * e0, m.y * e1);     B.y = pack2(m.z * e2, m.w * e3);
            A.x = pack2(-0.5f * e0, -0.5f * e1); A.y = pack2(-0.5f * e2, -0.5f * e3);
            sWB[jp2 * RW + k] = B;
            sWA[jp2 * RW + k] = A;
        }
        if (bad) atomicOr(sFlag, 1);
        if (t < GMM_K) {
            float s = 0.f;
            #pragma unroll 8
            for (int d = 0; d < GMM_D; d++) {
                float l = lv[t * GMM_D + d];
                float m = mu[t * GMM_D + d];
                s += l + m * m * __expf(-l);
            }
            sC[t] = -0.5f * s + lp[t];
        }
    }
    __syncthreads();                      // LAST block barrier

    const int general = *sFlag;
    float ck[8];
    #pragma unroll
    for (int q = 0; q < 8; q++) ck[q] = sC[kg + 8 * q];

    const ulonglong2* wb = sWB + kg;
    const ulonglong2* wa = sWA + kg;
    float* scr = (float*)(sm + OFF_SCR + warp * 2304);

    int bufi = 0;
    for (int chunk = gwarp; chunk < nchunks; chunk += nwarps) {
        const int nxt = chunk + nwarps;
        const uint32_t cur = bufi ? buf1 : buf0;
        __syncwarp();                     // prev-iter reads of the other buffer done
        if (nxt < nchunks) {
            prefetch_chunk(X, nxt, bufi ? buf0 : buf1, lane);
            cp_commit();
            cp_wait<1>();
        } else {
            cp_wait<0>();
        }
        __syncwarp();                     // all lanes' cp.async for cur visible

        const ulonglong2* xb = (const ulonglong2*)(sm + (cur - smem_u32(sm))) + sg;

        ull acc[8][8];
        #pragma unroll
        for (int m = 0; m < 8; m++)
            #pragma unroll
            for (int q = 0; q < 8; q++) acc[m][q] = 0ull;

        if (!general) {
            #pragma unroll
            for (int jp2 = 0; jp2 < NJ2; jp2++) {
                ulonglong2 wv[8], xv[8];
                #pragma unroll
                for (int q = 0; q < 8; q++) wv[q] = wb[jp2 * RW + 8 * q];
                #pragma unroll
                for (int m = 0; m < 8; m++) xv[m] = xb[jp2 * RXC + 4 * m];
                #pragma unroll
                for (int m = 0; m < 8; m++)
                    #pragma unroll
                    for (int q = 0; q < 8; q++) {
                        acc[m][q] = fma2(xv[m].x, wv[q].x, acc[m][q]);
                        acc[m][q] = fma2(xv[m].y, wv[q].y, acc[m][q]);
                    }
            }
        } else {
            #pragma unroll 2
            for (int jp2 = 0; jp2 < NJ2; jp2++) {
                ulonglong2 wv[8], wv2[8], xv[8];
                #pragma unroll
                for (int q = 0; q < 8; q++) { wv[q]  = wb[jp2 * RW + 8 * q];
                                              wv2[q] = wa[jp2 * RW + 8 * q]; }
                #pragma unroll
                for (int m = 0; m < 8; m++) xv[m] = xb[jp2 * RXC + 4 * m];
                #pragma unroll
                for (int m = 0; m < 8; m++) {
                    ull xqx = mul2(xv[m].x, xv[m].x);
                    ull xqy = mul2(xv[m].y, xv[m].y);
                    #pragma unroll
                    for (int q = 0; q < 8; q++) {
                        acc[m][q] = fma2(xv[m].x, wv[q].x, acc[m][q]);
                        acc[m][q] = fma2(xv[m].y, wv[q].y, acc[m][q]);
                        acc[m][q] = fma2(xqx, wv2[q].x, acc[m][q]);
                        acc[m][q] = fma2(xqy, wv2[q].y, acc[m][q]);
                    }
                }
            }
        }

        // ---- finalize + warp-local logsumexp over k ----
        float w[8][8], lse[8];
        #pragma unroll
        for (int q = 0; q < 8; q++)
            #pragma unroll
            for (int m = 0; m < 8; m++) {
                float lo, hi; unpack2(acc[m][q], lo, hi);
                w[m][q] = lo + hi + ck[q];
            }
        #pragma unroll
        for (int m = 0; m < 8; m++) {
            float mx = w[m][0];
            #pragma unroll
            for (int q = 1; q < 8; q++) mx = fmaxf(mx, w[m][q]);
            mx = fmaxf(mx, __shfl_xor_sync(0xffffffffu, mx, 4));
            mx = fmaxf(mx, __shfl_xor_sync(0xffffffffu, mx, 8));
            mx = fmaxf(mx, __shfl_xor_sync(0xffffffffu, mx, 16));
            float s = 0.f;
            #pragma unroll
            for (int q = 0; q < 8; q++) s += __expf(w[m][q] - mx);
            s += __shfl_xor_sync(0xffffffffu, s, 4);
            s += __shfl_xor_sync(0xffffffffu, s, 8);
            s += __shfl_xor_sync(0xffffffffu, s, 16);
            lse[m] = mx + __logf(s);
        }

        // ---- per-warp transpose scratch -> coalesced STG.128 ----
        const int n0c = chunk * WCH;
        #pragma unroll
        for (int p = 0; p < 4; p++) {     // 4 passes of 16 k-rows
            #pragma unroll
            for (int qq = 0; qq < 2; qq++) {
                const int q = 2 * p + qq;
                const int r = kg + 8 * qq;
                #pragma unroll
                for (int m = 0; m < 8; m++)
                    scr[r * SCR_STRIDE + sg + 4 * m] = w[m][q] - lse[m];
            }
            __syncwarp();
            #pragma unroll
            for (int j = 0; j < 4; j++) {
                const int r = j * 4 + (lane >> 3);
                const int c = 4 * (lane & 7);
                float4 v = *(const float4*)&scr[r * SCR_STRIDE + c];
                *(float4*)(out + (size_t)(16 * p + r) * N + n0c + c) = v;
            }
            __syncwarp();
        }
        bufi ^= 1;
    }
}

extern "C" void kernel_launch(void* const* d_in, const int* in_sizes, int n_in,
                              void* d_out, int out_size) {
    const float* X  = (const float*)d_in[0];
    const float* mu = (const float*)d_in[1];
    const float* lv = (const float*)d_in[2];
    const float* lp = (const float*)d_in[3];
    float* out = (float*)d_out;

    const int K = in_sizes[3];            // 64
    const int D = in_sizes[1] / K;        // 64
    const int N = in_sizes[0] / D;        // 131072

    const int nchunks = N / WCH;          // 4096
    int grid = 296;                       // 2 per SM x 148 SMs
    const int nwarps = grid * 4;

    cudaFuncSetAttribute(gmm_warp, cudaFuncAttributeMaxDynamicSharedMemorySize, SMEM_TOTAL);
    gmm_warp<<<grid, TPB, SMEM_TOTAL>>>(X, mu, lv, lp, out, N, nchunks, nwarps);
}